// round 3
// baseline (speedup 1.0000x reference)
#include <cuda_runtime.h>
#include <cstdint>

#define VOCAB  32000
#define EMBED  256
#define HIDDEN 512
#define BATCH  16
#define SEQ    512
#define BT     (BATCH * SEQ)   // 8192

__device__ float g_pre[2u * BT * HIDDEN];          // [dir][bt][h]
__device__ float g_hcat[(size_t)BT * 2 * HIDDEN];  // [bt][dir*H+h]

typedef unsigned long long u64;

__device__ __forceinline__ u64 fma2(u64 a, u64 b, u64 c) {
    u64 d;
    asm("fma.rn.f32x2 %0, %1, %2, %3;" : "=l"(d) : "l"(a), "l"(b), "l"(c));
    return d;
}
__device__ __forceinline__ u64 dup2(float x) {
    u64 d;
    asm("mov.b64 %0, {%1, %1};" : "=l"(d) : "f"(x));
    return d;
}
__device__ __forceinline__ float2 unp2(u64 v) {
    float2 r;
    asm("mov.b64 {%0, %1}, %2;" : "=f"(r.x), "=f"(r.y) : "l"(v));
    return r;
}

// ============ Kernel 1: pre = gather(emb) @ W_xh + b ============
// grid (128, 16): x = m-tile(64), y = dir*8 + n-tile(64). 256 thr, 4x4 micro.
__global__ __launch_bounds__(256) void pre_kernel(
    const int* __restrict__ inputs, const float* __restrict__ emb,
    const float* __restrict__ Wxf, const float* __restrict__ bhf,
    const float* __restrict__ Wxb, const float* __restrict__ bhb)
{
    __shared__ int   toks[64];
    __shared__ float As[32][65];
    __shared__ float Bs[32][64];

    const int tid = threadIdx.x;
    const int dir = blockIdx.y >> 3;
    const int n0  = (blockIdx.y & 7) * 64;
    const int m0  = blockIdx.x * 64;
    const float* W  = dir ? Wxb : Wxf;
    const float* bh = dir ? bhb : bhf;

    if (tid < 64) toks[tid] = inputs[m0 + tid];
    __syncthreads();

    const int ty = tid >> 4, tx = tid & 15;
    const int am = tid >> 2, akq = (tid & 3) * 4;
    const int bkr = tid >> 4, bc4 = (tid & 15) * 4;
    const size_t arow = (size_t)toks[am] * EMBED;

    float acc[4][4] = {};

    for (int k0 = 0; k0 < EMBED; k0 += 32) {
        float4 a0 = *(const float4*)&emb[arow + k0 + akq];
        float4 a1 = *(const float4*)&emb[arow + k0 + 16 + akq];
        float4 b0 = *(const float4*)&W[(size_t)(k0 + bkr) * HIDDEN + n0 + bc4];
        float4 b1 = *(const float4*)&W[(size_t)(k0 + bkr + 16) * HIDDEN + n0 + bc4];
        __syncthreads();
        As[akq + 0][am] = a0.x; As[akq + 1][am] = a0.y;
        As[akq + 2][am] = a0.z; As[akq + 3][am] = a0.w;
        As[akq + 16][am] = a1.x; As[akq + 17][am] = a1.y;
        As[akq + 18][am] = a1.z; As[akq + 19][am] = a1.w;
        *(float4*)&Bs[bkr][bc4]      = b0;
        *(float4*)&Bs[bkr + 16][bc4] = b1;
        __syncthreads();
        #pragma unroll
        for (int k = 0; k < 32; k++) {
            float4 bv = *(const float4*)&Bs[k][tx * 4];
            #pragma unroll
            for (int i = 0; i < 4; i++) {
                float a = As[k][ty * 4 + i];
                acc[i][0] += a * bv.x; acc[i][1] += a * bv.y;
                acc[i][2] += a * bv.z; acc[i][3] += a * bv.w;
            }
        }
    }

    float4 bias = *(const float4*)&bh[n0 + tx * 4];
    #pragma unroll
    for (int i = 0; i < 4; i++) {
        int row = m0 + ty * 4 + i;
        float4 o = make_float4(acc[i][0] + bias.x, acc[i][1] + bias.y,
                               acc[i][2] + bias.z, acc[i][3] + bias.w);
        *(float4*)&g_pre[((size_t)dir * BT + row) * HIDDEN + n0 + tx * 4] = o;
    }
}

// ============ Kernel 2: recurrent scan, 16 CTAs x 128 thr ============
__global__ __launch_bounds__(128) void scan_kernel(
    const float* __restrict__ hprev,
    const float* __restrict__ Whf, const float* __restrict__ Whb)
{
    __shared__ u64 h0d[HIDDEN];
    __shared__ u64 h1d[HIDDEN];

    const int tid = threadIdx.x;
    const int dir = blockIdx.x >> 3;
    const int b0  = (blockIdx.x & 7) * 2, b1 = b0 + 1;
    const int j4  = tid * 4;
    const float* W = dir ? Whb : Whf;
    const float* preBase = g_pre + (size_t)dir * BT * HIDDEN;

    {
        float4 h0 = *(const float4*)&hprev[b0 * HIDDEN + j4];
        float4 h1 = *(const float4*)&hprev[b1 * HIDDEN + j4];
        h0d[j4+0]=dup2(h0.x); h0d[j4+1]=dup2(h0.y); h0d[j4+2]=dup2(h0.z); h0d[j4+3]=dup2(h0.w);
        h1d[j4+0]=dup2(h1.x); h1d[j4+1]=dup2(h1.y); h1d[j4+2]=dup2(h1.z); h1d[j4+3]=dup2(h1.w);
    }
    __syncthreads();

    for (int s = 0; s < SEQ; s++) {
        const int t = dir ? (SEQ - 1 - s) : s;
        ulonglong2 a0 = *(const ulonglong2*)&preBase[((size_t)b0 * SEQ + t) * HIDDEN + j4];
        ulonglong2 a1 = *(const ulonglong2*)&preBase[((size_t)b1 * SEQ + t) * HIDDEN + j4];
        u64 acc00 = a0.x, acc01 = a0.y, acc10 = a1.x, acc11 = a1.y;

        #pragma unroll 4
        for (int k = 0; k < HIDDEN; k += 2) {
            ulonglong2 w0 = *(const ulonglong2*)&W[(size_t)k * HIDDEN + j4];
            ulonglong2 w1 = *(const ulonglong2*)&W[(size_t)(k + 1) * HIDDEN + j4];
            u64 hk0 = h0d[k], hk0b = h0d[k + 1];
            u64 hk1 = h1d[k], hk1b = h1d[k + 1];
            acc00 = fma2(hk0,  w0.x, acc00); acc01 = fma2(hk0,  w0.y, acc01);
            acc10 = fma2(hk1,  w0.x, acc10); acc11 = fma2(hk1,  w0.y, acc11);
            acc00 = fma2(hk0b, w1.x, acc00); acc01 = fma2(hk0b, w1.y, acc01);
            acc10 = fma2(hk1b, w1.x, acc10); acc11 = fma2(hk1b, w1.y, acc11);
        }

        float2 u00 = unp2(acc00), u01 = unp2(acc01);
        float2 u10 = unp2(acc10), u11 = unp2(acc11);
        float4 r0 = make_float4(tanhf(u00.x), tanhf(u00.y), tanhf(u01.x), tanhf(u01.y));
        float4 r1 = make_float4(tanhf(u10.x), tanhf(u10.y), tanhf(u11.x), tanhf(u11.y));

        __syncthreads();
        h0d[j4+0]=dup2(r0.x); h0d[j4+1]=dup2(r0.y); h0d[j4+2]=dup2(r0.z); h0d[j4+3]=dup2(r0.w);
        h1d[j4+0]=dup2(r1.x); h1d[j4+1]=dup2(r1.y); h1d[j4+2]=dup2(r1.z); h1d[j4+3]=dup2(r1.w);

        size_t o0 = ((size_t)b0 * SEQ + t) * (2 * HIDDEN) + (size_t)dir * HIDDEN + j4;
        size_t o1 = ((size_t)b1 * SEQ + t) * (2 * HIDDEN) + (size_t)dir * HIDDEN + j4;
        *(float4*)&g_hcat[o0] = r0;
        *(float4*)&g_hcat[o1] = r1;
        __syncthreads();
    }
}

// ============ Kernel 3: out = hcat @ W_fc + b_fc ============
// M=8192, N=32000, K=1024. 128x128 tile, BK=16, 256 thr, 8x8 micro, f32x2.
__global__ __launch_bounds__(256, 2) void fc_kernel(
    const float* __restrict__ Wfc, const float* __restrict__ bfc,
    float* __restrict__ out)
{
    __shared__ float As[16][132];
    __shared__ float Bs[16][128];

    const int tid = threadIdx.x;
    const int n0 = blockIdx.x * 128;
    const int m0 = blockIdx.y * 128;
    const int tx = tid & 15, ty = tid >> 4;
    const int ar = tid >> 1, ak = (tid & 1) * 8;
    const int br = tid >> 5, bc = (tid & 31) * 4;
    const float* A = g_hcat;

    u64 d[8][4];
    #pragma unroll
    for (int m = 0; m < 8; m++) { d[m][0]=0; d[m][1]=0; d[m][2]=0; d[m][3]=0; }

    float4 pa0 = *(const float4*)&A[(size_t)(m0 + ar) * 1024 + ak];
    float4 pa1 = *(const float4*)&A[(size_t)(m0 + ar) * 1024 + ak + 4];
    float4 pb0 = *(const float4*)&Wfc[(size_t)br * VOCAB + n0 + bc];
    float4 pb1 = *(const float4*)&Wfc[(size_t)(br + 8) * VOCAB + n0 + bc];

    for (int kt = 0; kt < 64; kt++) {
        __syncthreads();
        As[ak + 0][ar] = pa0.x; As[ak + 1][ar] = pa0.y;
        As[ak + 2][ar] = pa0.z; As[ak + 3][ar] = pa0.w;
        As[ak + 4][ar] = pa1.x; As[ak + 5][ar] = pa1.y;
        As[ak + 6][ar] = pa1.z; As[ak + 7][ar] = pa1.w;
        *(float4*)&Bs[br][bc]     = pb0;
        *(float4*)&Bs[br + 8][bc] = pb1;
        __syncthreads();

        if (kt < 63) {
            int k0 = (kt + 1) * 16;
            pa0 = *(const float4*)&A[(size_t)(m0 + ar) * 1024 + k0 + ak];
            pa1 = *(const float4*)&A[(size_t)(m0 + ar) * 1024 + k0 + ak + 4];
            pb0 = *(const float4*)&Wfc[(size_t)(k0 + br) * VOCAB + n0 + bc];
            pb1 = *(const float4*)&Wfc[(size_t)(k0 + br + 8) * VOCAB + n0 + bc];
        }

        #pragma unroll
        for (int k = 0; k < 16; k++) {
            ulonglong2 bv0 = *(const ulonglong2*)&Bs[k][tx * 4];
            ulonglong2 bv1 = *(const ulonglong2*)&Bs[k][64 + tx * 4];
            #pragma unroll
            for (int m = 0; m < 8; m++) {
                u64 av = dup2(As[k][ty * 8 + m]);
                d[m][0] = fma2(av, bv0.x, d[m][0]);
                d[m][1] = fma2(av, bv0.y, d[m][1]);
                d[m][2] = fma2(av, bv1.x, d[m][2]);
                d[m][3] = fma2(av, bv1.y, d[m][3]);
            }
        }
    }

    float4 bb0 = *(const float4*)&bfc[n0 + tx * 4];
    float4 bb1 = *(const float4*)&bfc[n0 + 64 + tx * 4];
    #pragma unroll
    for (int m = 0; m < 8; m++) {
        int row = m0 + ty * 8 + m;
        float2 v0 = unp2(d[m][0]), v1 = unp2(d[m][1]);
        float2 v2 = unp2(d[m][2]), v3 = unp2(d[m][3]);
        float4 o0 = make_float4(v0.x + bb0.x, v0.y + bb0.y, v1.x + bb0.z, v1.y + bb0.w);
        float4 o1 = make_float4(v2.x + bb1.x, v2.y + bb1.y, v3.x + bb1.z, v3.y + bb1.w);
        *(float4*)&out[(size_t)row * VOCAB + n0 + tx * 4]      = o0;
        *(float4*)&out[(size_t)row * VOCAB + n0 + 64 + tx * 4] = o1;
    }
}

extern "C" void kernel_launch(void* const* d_in, const int* in_sizes, int n_in,
                              void* d_out, int out_size) {
    const int*   inputs = (const int*)  d_in[0];
    const float* h_prev = (const float*)d_in[1];
    const float* emb    = (const float*)d_in[2];
    const float* W_xh_f = (const float*)d_in[3];
    const float* W_hh_f = (const float*)d_in[4];
    const float* b_h_f  = (const float*)d_in[5];
    const float* W_xh_b = (const float*)d_in[6];
    const float* W_hh_b = (const float*)d_in[7];
    const float* b_h_b  = (const float*)d_in[8];
    const float* W_fc   = (const float*)d_in[9];
    const float* b_fc   = (const float*)d_in[10];
    float* out = (float*)d_out;

    pre_kernel<<<dim3(BT / 64, 16), 256>>>(inputs, emb, W_xh_f, b_h_f, W_xh_b, b_h_b);
    scan_kernel<<<16, 128>>>(h_prev, W_hh_f, W_hh_b);
    fc_kernel<<<dim3(VOCAB / 128, BT / 128), 256>>>(W_fc, b_fc, out);
}

// round 5
// speedup vs baseline: 2.4148x; 2.4148x over previous
#include <cuda_runtime.h>
#include <cuda_bf16.h>
#include <cstdint>

#define VOCAB  32000
#define EMBED  256
#define HIDDEN 512
#define BATCH  16
#define SEQ    512
#define BT     (BATCH * SEQ)   // 8192
#define KDIM   1024            // 2*HIDDEN

typedef unsigned long long u64;

// ---------------- scratch (static device arrays) ----------------
__device__ float         g_pre[2u * BT * HIDDEN];          // [dir][bt][h]
__device__ __nv_bfloat16 gAhi[(size_t)BT * KDIM];          // hcat hi limb [bt][k]
__device__ __nv_bfloat16 gAlo[(size_t)BT * KDIM];          // hcat lo limb
__device__ __nv_bfloat16 gBhi[(size_t)VOCAB * KDIM];       // W_fc^T hi [n][k]
__device__ __nv_bfloat16 gBlo[(size_t)VOCAB * KDIM];       // W_fc^T lo

// ---------------- f32x2 helpers ----------------
__device__ __forceinline__ u64 fma2(u64 a, u64 b, u64 c) {
    u64 d; asm("fma.rn.f32x2 %0, %1, %2, %3;" : "=l"(d) : "l"(a), "l"(b), "l"(c)); return d;
}
__device__ __forceinline__ u64 add2(u64 a, u64 b) {
    u64 d; asm("add.rn.f32x2 %0, %1, %2;" : "=l"(d) : "l"(a), "l"(b)); return d;
}
__device__ __forceinline__ u64 dup2(float x) {
    u64 d; asm("mov.b64 %0, {%1, %1};" : "=l"(d) : "f"(x)); return d;
}
__device__ __forceinline__ float2 unp2(u64 v) {
    float2 r; asm("mov.b64 {%0, %1}, %2;" : "=f"(r.x), "=f"(r.y) : "l"(v)); return r;
}

// ---------------- cp.async / smem helpers ----------------
__device__ __forceinline__ uint32_t smem_u32(const void* p) {
    uint32_t a;
    asm("{ .reg .u64 t; cvta.to.shared.u64 t, %1; cvt.u32.u64 %0, t; }" : "=r"(a) : "l"(p));
    return a;
}
__device__ __forceinline__ void cpa16(uint32_t dst, const void* src) {
    asm volatile("cp.async.cg.shared.global [%0], [%1], 16;" :: "r"(dst), "l"(src));
}
__device__ __forceinline__ void cpa_commit() { asm volatile("cp.async.commit_group;" ::: "memory"); }
__device__ __forceinline__ void cpa_wait1()  { asm volatile("cp.async.wait_group 1;"  ::: "memory"); }
__device__ __forceinline__ void cpa_wait0()  { asm volatile("cp.async.wait_group 0;"  ::: "memory"); }

// ---------------- mma.sync / ldmatrix ----------------
__device__ __forceinline__ void ldsm4(uint32_t* r, uint32_t addr) {
    asm volatile("ldmatrix.sync.aligned.m8n8.x4.shared.b16 {%0,%1,%2,%3}, [%4];"
                 : "=r"(r[0]), "=r"(r[1]), "=r"(r[2]), "=r"(r[3]) : "r"(addr));
}
__device__ __forceinline__ void mma_bf16(float* c, const uint32_t* a, uint32_t b0, uint32_t b1) {
    asm volatile("mma.sync.aligned.m16n8k16.row.col.f32.bf16.bf16.f32 "
                 "{%0,%1,%2,%3}, {%4,%5,%6,%7}, {%8,%9}, {%0,%1,%2,%3};"
                 : "+f"(c[0]), "+f"(c[1]), "+f"(c[2]), "+f"(c[3])
                 : "r"(a[0]), "r"(a[1]), "r"(a[2]), "r"(a[3]), "r"(b0), "r"(b1));
}

__device__ __forceinline__ void split2(float x, float y, uint32_t& hi, uint32_t& lo) {
    __nv_bfloat16 hx = __float2bfloat16(x), hy = __float2bfloat16(y);
    float rx = x - __bfloat162float(hx), ry = y - __bfloat162float(hy);
    __nv_bfloat16 lx = __float2bfloat16(rx), ly = __float2bfloat16(ry);
    hi = ((uint32_t)__bfloat16_as_ushort(hy) << 16) | __bfloat16_as_ushort(hx);
    lo = ((uint32_t)__bfloat16_as_ushort(ly) << 16) | __bfloat16_as_ushort(lx);
}

// ============ Kernel 1: pre = gather(emb) @ W_xh + b ============
__global__ __launch_bounds__(256) void pre_kernel(
    const int* __restrict__ inputs, const float* __restrict__ emb,
    const float* __restrict__ Wxf, const float* __restrict__ bhf,
    const float* __restrict__ Wxb, const float* __restrict__ bhb)
{
    __shared__ int   toks[64];
    __shared__ float As[32][65];
    __shared__ float Bs[32][64];

    const int tid = threadIdx.x;
    const int dir = blockIdx.y >> 3;
    const int n0  = (blockIdx.y & 7) * 64;
    const int m0  = blockIdx.x * 64;
    const float* W  = dir ? Wxb : Wxf;
    const float* bh = dir ? bhb : bhf;

    if (tid < 64) toks[tid] = inputs[m0 + tid];
    __syncthreads();

    const int ty = tid >> 4, tx = tid & 15;
    const int am = tid >> 2, akq = (tid & 3) * 4;
    const int bkr = tid >> 4, bc4 = (tid & 15) * 4;
    const size_t arow = (size_t)toks[am] * EMBED;

    float acc[4][4] = {};

    for (int k0 = 0; k0 < EMBED; k0 += 32) {
        float4 a0 = *(const float4*)&emb[arow + k0 + akq];
        float4 a1 = *(const float4*)&emb[arow + k0 + 16 + akq];
        float4 b0 = *(const float4*)&W[(size_t)(k0 + bkr) * HIDDEN + n0 + bc4];
        float4 b1 = *(const float4*)&W[(size_t)(k0 + bkr + 16) * HIDDEN + n0 + bc4];
        __syncthreads();
        As[akq + 0][am] = a0.x; As[akq + 1][am] = a0.y;
        As[akq + 2][am] = a0.z; As[akq + 3][am] = a0.w;
        As[akq + 16][am] = a1.x; As[akq + 17][am] = a1.y;
        As[akq + 18][am] = a1.z; As[akq + 19][am] = a1.w;
        *(float4*)&Bs[bkr][bc4]      = b0;
        *(float4*)&Bs[bkr + 16][bc4] = b1;
        __syncthreads();
        #pragma unroll
        for (int k = 0; k < 32; k++) {
            float4 bv = *(const float4*)&Bs[k][tx * 4];
            #pragma unroll
            for (int i = 0; i < 4; i++) {
                float a = As[k][ty * 4 + i];
                acc[i][0] += a * bv.x; acc[i][1] += a * bv.y;
                acc[i][2] += a * bv.z; acc[i][3] += a * bv.w;
            }
        }
    }

    float4 bias = *(const float4*)&bh[n0 + tx * 4];
    #pragma unroll
    for (int i = 0; i < 4; i++) {
        int row = m0 + ty * 4 + i;
        float4 o = make_float4(acc[i][0] + bias.x, acc[i][1] + bias.y,
                               acc[i][2] + bias.z, acc[i][3] + bias.w);
        *(float4*)&g_pre[((size_t)dir * BT + row) * HIDDEN + n0 + tx * 4] = o;
    }
}

// ============ Kernel 2: W_fc transpose + bf16 limb split ============
__global__ __launch_bounds__(256) void convw_kernel(const float* __restrict__ W)
{
    __shared__ float s[32][33];
    const int k0 = blockIdx.x * 32;
    const int n0 = blockIdx.y * 32;
    const int tx = threadIdx.x & 31, ty = threadIdx.x >> 5;

    #pragma unroll
    for (int j = 0; j < 4; j++) {
        int ky = ty + 8 * j;
        s[ky][tx] = W[(size_t)(k0 + ky) * VOCAB + n0 + tx];
    }
    __syncthreads();
    #pragma unroll
    for (int j = 0; j < 4; j++) {
        int ny = ty + 8 * j;
        float v = s[tx][ny];
        __nv_bfloat16 hi = __float2bfloat16(v);
        __nv_bfloat16 lo = __float2bfloat16(v - __bfloat162float(hi));
        size_t o = (size_t)(n0 + ny) * KDIM + k0 + tx;
        gBhi[o] = hi; gBlo[o] = lo;
    }
}

// ============ Kernel 3: recurrent scan (k-split, 256 thr), emits bf16 limbs ============
__global__ __launch_bounds__(256) void scan_kernel(
    const float* __restrict__ hprev,
    const float* __restrict__ Whf, const float* __restrict__ Whb)
{
    __shared__ u64 h0d[HIDDEN];
    __shared__ u64 h1d[HIDDEN];
    __shared__ u64 part[128][4];

    const int tid  = threadIdx.x;
    const int half = tid >> 7;
    const int lt   = tid & 127;
    const int j4   = lt * 4;
    const int dir  = blockIdx.x >> 3;
    const int b0   = (blockIdx.x & 7) * 2, b1 = b0 + 1;
    const int kbase = half * 256;
    const float* W = dir ? Whb : Whf;
    const float* preBase = g_pre + (size_t)dir * BT * HIDDEN;

    if (half == 0) {
        float4 h0 = *(const float4*)&hprev[b0 * HIDDEN + j4];
        float4 h1 = *(const float4*)&hprev[b1 * HIDDEN + j4];
        h0d[j4+0]=dup2(h0.x); h0d[j4+1]=dup2(h0.y); h0d[j4+2]=dup2(h0.z); h0d[j4+3]=dup2(h0.w);
        h1d[j4+0]=dup2(h1.x); h1d[j4+1]=dup2(h1.y); h1d[j4+2]=dup2(h1.z); h1d[j4+3]=dup2(h1.w);
    }
    __syncthreads();

    const float* Wr = W + (size_t)kbase * HIDDEN;

    for (int s = 0; s < SEQ; s++) {
        const int t = dir ? (SEQ - 1 - s) : s;
        u64 acc00, acc01, acc10, acc11;
        if (half == 0) {
            ulonglong2 a0 = *(const ulonglong2*)&preBase[((size_t)b0 * SEQ + t) * HIDDEN + j4];
            ulonglong2 a1 = *(const ulonglong2*)&preBase[((size_t)b1 * SEQ + t) * HIDDEN + j4];
            acc00 = a0.x; acc01 = a0.y; acc10 = a1.x; acc11 = a1.y;
        } else {
            acc00 = 0; acc01 = 0; acc10 = 0; acc11 = 0;
        }

        #pragma unroll 4
        for (int kp = 0; kp < 128; kp++) {
            int k = kbase + 2 * kp;
            ulonglong2 w0 = *(const ulonglong2*)&Wr[(size_t)(2 * kp) * HIDDEN + j4];
            ulonglong2 w1 = *(const ulonglong2*)&Wr[(size_t)(2 * kp + 1) * HIDDEN + j4];
            u64 hk0 = h0d[k], hk0b = h0d[k + 1];
            u64 hk1 = h1d[k], hk1b = h1d[k + 1];
            acc00 = fma2(hk0,  w0.x, acc00); acc01 = fma2(hk0,  w0.y, acc01);
            acc10 = fma2(hk1,  w0.x, acc10); acc11 = fma2(hk1,  w0.y, acc11);
            acc00 = fma2(hk0b, w1.x, acc00); acc01 = fma2(hk0b, w1.y, acc01);
            acc10 = fma2(hk1b, w1.x, acc10); acc11 = fma2(hk1b, w1.y, acc11);
        }

        if (half == 1) {
            part[lt][0] = acc00; part[lt][1] = acc01;
            part[lt][2] = acc10; part[lt][3] = acc11;
        }
        __syncthreads();

        if (half == 0) {
            acc00 = add2(acc00, part[lt][0]); acc01 = add2(acc01, part[lt][1]);
            acc10 = add2(acc10, part[lt][2]); acc11 = add2(acc11, part[lt][3]);

            float2 u00 = unp2(acc00), u01 = unp2(acc01);
            float2 u10 = unp2(acc10), u11 = unp2(acc11);
            float4 r0 = make_float4(tanhf(u00.x), tanhf(u00.y), tanhf(u01.x), tanhf(u01.y));
            float4 r1 = make_float4(tanhf(u10.x), tanhf(u10.y), tanhf(u11.x), tanhf(u11.y));

            h0d[j4+0]=dup2(r0.x); h0d[j4+1]=dup2(r0.y); h0d[j4+2]=dup2(r0.z); h0d[j4+3]=dup2(r0.w);
            h1d[j4+0]=dup2(r1.x); h1d[j4+1]=dup2(r1.y); h1d[j4+2]=dup2(r1.z); h1d[j4+3]=dup2(r1.w);

            uint32_t hA, lA, hB, lB;
            size_t row0 = ((size_t)b0 * SEQ + t) * KDIM + dir * HIDDEN + j4;
            size_t row1 = ((size_t)b1 * SEQ + t) * KDIM + dir * HIDDEN + j4;
            split2(r0.x, r0.y, hA, lA); split2(r0.z, r0.w, hB, lB);
            *(uint2*)&gAhi[row0] = make_uint2(hA, hB);
            *(uint2*)&gAlo[row0] = make_uint2(lA, lB);
            split2(r1.x, r1.y, hA, lA); split2(r1.z, r1.w, hB, lB);
            *(uint2*)&gAhi[row1] = make_uint2(hA, hB);
            *(uint2*)&gAlo[row1] = make_uint2(lA, lB);
        }
        __syncthreads();
    }
}

// ============ Kernel 4: FC GEMM via mma.sync bf16, 2-limb, 3 terms ============
// CTA 128x128, BK=32, 2-stage cp.async pipeline. smem rows padded to 80B.
#define RSB    80
#define TILEB  (128 * RSB)      // 10240
#define STAGEB (4 * TILEB)      // 40960
#define FC_SMEM (2 * STAGEB)    // 81920

__device__ __forceinline__ void fc_load_stage(
    uint32_t base, int kc, int m0, int n0, int tid)
{
    const int k0 = kc * 32;
    const __nv_bfloat16* srcs[4] = {
        gAhi + (size_t)m0 * KDIM, gAlo + (size_t)m0 * KDIM,
        gBhi + (size_t)n0 * KDIM, gBlo + (size_t)n0 * KDIM };
    #pragma unroll
    for (int t = 0; t < 4; t++) {
        #pragma unroll
        for (int j = 0; j < 2; j++) {
            int u = tid + 256 * j;
            int row = u >> 2, c = u & 3;
            cpa16(base + t * TILEB + row * RSB + c * 16,
                  srcs[t] + (size_t)row * KDIM + k0 + c * 8);
        }
    }
    cpa_commit();
}

__global__ __launch_bounds__(256, 2) void fc_kernel(
    const float* __restrict__ bfc, float* __restrict__ out)
{
    extern __shared__ char smem[];
    const uint32_t sb = smem_u32(smem);
    const int tid = threadIdx.x, lane = tid & 31, wid = tid >> 5;
    const int mw = wid & 1, nw = wid >> 1;
    const int m0 = blockIdx.x * 128, n0 = blockIdx.y * 128;

    // per-lane ldmatrix address components
    const int q = lane >> 3, r = lane & 7;
    const uint32_t aOff = (uint32_t)((mw * 64 + (q & 1) * 8 + r) * RSB + ((q >> 1) * 8) * 2);
    const uint32_t bOff = (uint32_t)((nw * 32 + (q >> 1) * 8 + r) * RSB + ((q & 1) * 8) * 2);

    float acc[4][4][4];
    #pragma unroll
    for (int i = 0; i < 4; i++)
        #pragma unroll
        for (int j = 0; j < 4; j++) {
            acc[i][j][0] = 0.f; acc[i][j][1] = 0.f;
            acc[i][j][2] = 0.f; acc[i][j][3] = 0.f;
        }

    fc_load_stage(sb, 0, m0, n0, tid);
    fc_load_stage(sb + STAGEB, 1, m0, n0, tid);

    for (int kc = 0; kc < 32; kc++) {
        const uint32_t bb = sb + (uint32_t)(kc & 1) * STAGEB;

        if (kc == 31) cpa_wait0(); else cpa_wait1();
        __syncthreads();

        #pragma unroll
        for (int j16 = 0; j16 < 2; j16++) {
            const uint32_t kb = (uint32_t)j16 * 32;   // 16 halves * 2B

            uint32_t ah[4][4], bh[2][4], bx[2][4], al[4][4];
            #pragma unroll
            for (int mf = 0; mf < 4; mf++)
                ldsm4(ah[mf], bb + aOff + mf * (16 * RSB) + kb);
            #pragma unroll
            for (int nf2 = 0; nf2 < 2; nf2++)
                ldsm4(bh[nf2], bb + 2 * TILEB + bOff + nf2 * (16 * RSB) + kb);

            // pass 1: ah * bh
            #pragma unroll
            for (int mf = 0; mf < 4; mf++)
                #pragma unroll
                for (int nf2 = 0; nf2 < 2; nf2++) {
                    mma_bf16(acc[mf][nf2 * 2],     ah[mf], bh[nf2][0], bh[nf2][1]);
                    mma_bf16(acc[mf][nf2 * 2 + 1], ah[mf], bh[nf2][2], bh[nf2][3]);
                }

            // pass 2: ah * bl
            #pragma unroll
            for (int nf2 = 0; nf2 < 2; nf2++)
                ldsm4(bx[nf2], bb + 3 * TILEB + bOff + nf2 * (16 * RSB) + kb);
            #pragma unroll
            for (int mf = 0; mf < 4; mf++)
                #pragma unroll
                for (int nf2 = 0; nf2 < 2; nf2++) {
                    mma_bf16(acc[mf][nf2 * 2],     ah[mf], bx[nf2][0], bx[nf2][1]);
                    mma_bf16(acc[mf][nf2 * 2 + 1], ah[mf], bx[nf2][2], bx[nf2][3]);
                }

            // pass 3: al * bh
            #pragma unroll
            for (int mf = 0; mf < 4; mf++)
                ldsm4(al[mf], bb + TILEB + aOff + mf * (16 * RSB) + kb);
            #pragma unroll
            for (int mf = 0; mf < 4; mf++)
                #pragma unroll
                for (int nf2 = 0; nf2 < 2; nf2++) {
                    mma_bf16(acc[mf][nf2 * 2],     al[mf], bh[nf2][0], bh[nf2][1]);
                    mma_bf16(acc[mf][nf2 * 2 + 1], al[mf], bh[nf2][2], bh[nf2][3]);
                }
        }

        __syncthreads();
        if (kc < 30) fc_load_stage(bb, kc + 2, m0, n0, tid);
    }

    // epilogue: registers -> gmem with bias
    #pragma unroll
    for (int mf = 0; mf < 4; mf++) {
        const int row = m0 + mw * 64 + mf * 16 + (lane >> 2);
        #pragma unroll
        for (int nf = 0; nf < 4; nf++) {
            const int col = n0 + nw * 32 + nf * 8 + 2 * (lane & 3);
            const float2 bb2 = __ldg((const float2*)&bfc[col]);
            float2 v0 = make_float2(acc[mf][nf][0] + bb2.x, acc[mf][nf][1] + bb2.y);
            float2 v1 = make_float2(acc[mf][nf][2] + bb2.x, acc[mf][nf][3] + bb2.y);
            *(float2*)&out[(size_t)row * VOCAB + col]       = v0;
            *(float2*)&out[(size_t)(row + 8) * VOCAB + col] = v1;
        }
    }
}

// ============ launch ============
extern "C" void kernel_launch(void* const* d_in, const int* in_sizes, int n_in,
                              void* d_out, int out_size) {
    const int*   inputs = (const int*)  d_in[0];
    const float* h_prev = (const float*)d_in[1];
    const float* emb    = (const float*)d_in[2];
    const float* W_xh_f = (const float*)d_in[3];
    const float* W_hh_f = (const float*)d_in[4];
    const float* b_h_f  = (const float*)d_in[5];
    const float* W_xh_b = (const float*)d_in[6];
    const float* W_hh_b = (const float*)d_in[7];
    const float* b_h_b  = (const float*)d_in[8];
    const float* W_fc   = (const float*)d_in[9];
    const float* b_fc   = (const float*)d_in[10];
    float* out = (float*)d_out;

    cudaFuncSetAttribute(fc_kernel, cudaFuncAttributeMaxDynamicSharedMemorySize, FC_SMEM);

    pre_kernel<<<dim3(BT / 64, 16), 256>>>(inputs, emb, W_xh_f, b_h_f, W_xh_b, b_h_b);
    convw_kernel<<<dim3(KDIM / 32, VOCAB / 32), 256>>>(W_fc);
    scan_kernel<<<16, 256>>>(h_prev, W_hh_f, W_hh_b);
    fc_kernel<<<dim3(BT / 128, VOCAB / 128), 256, FC_SMEM>>>(b_fc, out);
}

// round 7
// speedup vs baseline: 2.9431x; 1.2188x over previous
#include <cuda_runtime.h>
#include <cuda_bf16.h>
#include <cuda_fp16.h>
#include <cstdint>

#define VOCAB  32000
#define EMBED  256
#define HIDDEN 512
#define BATCH  16
#define SEQ    512
#define BT     (BATCH * SEQ)   // 8192
#define KDIM   1024            // 2*HIDDEN

typedef unsigned long long u64;

// ---------------- scratch (static device arrays) ----------------
__device__ float  g_pre[2u * BT * HIDDEN];        // [dir][bt][h]
__device__ __half gA[(size_t)BT * KDIM];          // hcat fp16 [bt][k]
__device__ __half gB[(size_t)VOCAB * KDIM];       // W_fc^T fp16 [n][k]

// ---------------- f32x2 helpers ----------------
__device__ __forceinline__ u64 fma2(u64 a, u64 b, u64 c) {
    u64 d; asm("fma.rn.f32x2 %0, %1, %2, %3;" : "=l"(d) : "l"(a), "l"(b), "l"(c)); return d;
}
__device__ __forceinline__ u64 add2(u64 a, u64 b) {
    u64 d; asm("add.rn.f32x2 %0, %1, %2;" : "=l"(d) : "l"(a), "l"(b)); return d;
}
__device__ __forceinline__ u64 dup2(float x) {
    u64 d; asm("mov.b64 %0, {%1, %1};" : "=l"(d) : "f"(x)); return d;
}
__device__ __forceinline__ float2 unp2(u64 v) {
    float2 r; asm("mov.b64 {%0, %1}, %2;" : "=f"(r.x), "=f"(r.y) : "l"(v)); return r;
}

// ---------------- cp.async / smem helpers ----------------
__device__ __forceinline__ uint32_t smem_u32(const void* p) {
    uint32_t a;
    asm("{ .reg .u64 t; cvta.to.shared.u64 t, %1; cvt.u32.u64 %0, t; }" : "=r"(a) : "l"(p));
    return a;
}
__device__ __forceinline__ void cpa16(uint32_t dst, const void* src) {
    asm volatile("cp.async.cg.shared.global [%0], [%1], 16;" :: "r"(dst), "l"(src));
}
__device__ __forceinline__ void cpa_commit() { asm volatile("cp.async.commit_group;" ::: "memory"); }
__device__ __forceinline__ void cpa_wait2()  { asm volatile("cp.async.wait_group 2;"  ::: "memory"); }
__device__ __forceinline__ void cpa_wait1()  { asm volatile("cp.async.wait_group 1;"  ::: "memory"); }
__device__ __forceinline__ void cpa_wait0()  { asm volatile("cp.async.wait_group 0;"  ::: "memory"); }

// ---------------- mma.sync / ldmatrix ----------------
__device__ __forceinline__ void ldsm4(uint32_t* r, uint32_t addr) {
    asm volatile("ldmatrix.sync.aligned.m8n8.x4.shared.b16 {%0,%1,%2,%3}, [%4];"
                 : "=r"(r[0]), "=r"(r[1]), "=r"(r[2]), "=r"(r[3]) : "r"(addr));
}
__device__ __forceinline__ void mma_fp16(float* c, const uint32_t* a, uint32_t b0, uint32_t b1) {
    asm volatile("mma.sync.aligned.m16n8k16.row.col.f32.f16.f16.f32 "
                 "{%0,%1,%2,%3}, {%4,%5,%6,%7}, {%8,%9}, {%0,%1,%2,%3};"
                 : "+f"(c[0]), "+f"(c[1]), "+f"(c[2]), "+f"(c[3])
                 : "r"(a[0]), "r"(a[1]), "r"(a[2]), "r"(a[3]), "r"(b0), "r"(b1));
}

// ============ Kernel 1: pre = gather(emb) @ W_xh + b ============
__global__ __launch_bounds__(256) void pre_kernel(
    const int* __restrict__ inputs, const float* __restrict__ emb,
    const float* __restrict__ Wxf, const float* __restrict__ bhf,
    const float* __restrict__ Wxb, const float* __restrict__ bhb)
{
    __shared__ int   toks[64];
    __shared__ float As[32][65];
    __shared__ float Bs[32][64];

    const int tid = threadIdx.x;
    const int dir = blockIdx.y >> 3;
    const int n0  = (blockIdx.y & 7) * 64;
    const int m0  = blockIdx.x * 64;
    const float* W  = dir ? Wxb : Wxf;
    const float* bh = dir ? bhb : bhf;

    if (tid < 64) toks[tid] = inputs[m0 + tid];
    __syncthreads();

    const int ty = tid >> 4, tx = tid & 15;
    const int am = tid >> 2, akq = (tid & 3) * 4;
    const int bkr = tid >> 4, bc4 = (tid & 15) * 4;
    const size_t arow = (size_t)toks[am] * EMBED;

    float acc[4][4] = {};

    for (int k0 = 0; k0 < EMBED; k0 += 32) {
        float4 a0 = *(const float4*)&emb[arow + k0 + akq];
        float4 a1 = *(const float4*)&emb[arow + k0 + 16 + akq];
        float4 b0 = *(const float4*)&W[(size_t)(k0 + bkr) * HIDDEN + n0 + bc4];
        float4 b1 = *(const float4*)&W[(size_t)(k0 + bkr + 16) * HIDDEN + n0 + bc4];
        __syncthreads();
        As[akq + 0][am] = a0.x; As[akq + 1][am] = a0.y;
        As[akq + 2][am] = a0.z; As[akq + 3][am] = a0.w;
        As[akq + 16][am] = a1.x; As[akq + 17][am] = a1.y;
        As[akq + 18][am] = a1.z; As[akq + 19][am] = a1.w;
        *(float4*)&Bs[bkr][bc4]      = b0;
        *(float4*)&Bs[bkr + 16][bc4] = b1;
        __syncthreads();
        #pragma unroll
        for (int k = 0; k < 32; k++) {
            float4 bv = *(const float4*)&Bs[k][tx * 4];
            #pragma unroll
            for (int i = 0; i < 4; i++) {
                float a = As[k][ty * 4 + i];
                acc[i][0] += a * bv.x; acc[i][1] += a * bv.y;
                acc[i][2] += a * bv.z; acc[i][3] += a * bv.w;
            }
        }
    }

    float4 bias = *(const float4*)&bh[n0 + tx * 4];
    #pragma unroll
    for (int i = 0; i < 4; i++) {
        int row = m0 + ty * 4 + i;
        float4 o = make_float4(acc[i][0] + bias.x, acc[i][1] + bias.y,
                               acc[i][2] + bias.z, acc[i][3] + bias.w);
        *(float4*)&g_pre[((size_t)dir * BT + row) * HIDDEN + n0 + tx * 4] = o;
    }
}

// ============ Kernel 2: W_fc transpose -> fp16 [n][k] ============
__global__ __launch_bounds__(256) void convw_kernel(const float* __restrict__ W)
{
    __shared__ float s[32][33];
    const int k0 = blockIdx.x * 32;
    const int n0 = blockIdx.y * 32;
    const int tx = threadIdx.x & 31, ty = threadIdx.x >> 5;

    #pragma unroll
    for (int j = 0; j < 4; j++) {
        int ky = ty + 8 * j;
        s[ky][tx] = W[(size_t)(k0 + ky) * VOCAB + n0 + tx];
    }
    __syncthreads();
    #pragma unroll
    for (int j = 0; j < 4; j++) {
        int ny = ty + 8 * j;
        gB[(size_t)(n0 + ny) * KDIM + k0 + tx] = __float2half_rn(s[tx][ny]);
    }
}

// ============ Kernel 3: recurrent scan (k-split, 256 thr), emits fp16 ============
__global__ __launch_bounds__(256) void scan_kernel(
    const float* __restrict__ hprev,
    const float* __restrict__ Whf, const float* __restrict__ Whb)
{
    __shared__ u64 h0d[HIDDEN];
    __shared__ u64 h1d[HIDDEN];
    __shared__ u64 part[128][4];

    const int tid  = threadIdx.x;
    const int half = tid >> 7;
    const int lt   = tid & 127;
    const int j4   = lt * 4;
    const int dir  = blockIdx.x >> 3;
    const int b0   = (blockIdx.x & 7) * 2, b1 = b0 + 1;
    const int kbase = half * 256;
    const float* W = dir ? Whb : Whf;
    const float* preBase = g_pre + (size_t)dir * BT * HIDDEN;

    if (half == 0) {
        float4 h0 = *(const float4*)&hprev[b0 * HIDDEN + j4];
        float4 h1 = *(const float4*)&hprev[b1 * HIDDEN + j4];
        h0d[j4+0]=dup2(h0.x); h0d[j4+1]=dup2(h0.y); h0d[j4+2]=dup2(h0.z); h0d[j4+3]=dup2(h0.w);
        h1d[j4+0]=dup2(h1.x); h1d[j4+1]=dup2(h1.y); h1d[j4+2]=dup2(h1.z); h1d[j4+3]=dup2(h1.w);
    }
    __syncthreads();

    const float* Wr = W + (size_t)kbase * HIDDEN;

    for (int s = 0; s < SEQ; s++) {
        const int t = dir ? (SEQ - 1 - s) : s;
        u64 acc00, acc01, acc10, acc11;
        if (half == 0) {
            ulonglong2 a0 = *(const ulonglong2*)&preBase[((size_t)b0 * SEQ + t) * HIDDEN + j4];
            ulonglong2 a1 = *(const ulonglong2*)&preBase[((size_t)b1 * SEQ + t) * HIDDEN + j4];
            acc00 = a0.x; acc01 = a0.y; acc10 = a1.x; acc11 = a1.y;
        } else {
            acc00 = 0; acc01 = 0; acc10 = 0; acc11 = 0;
        }

        #pragma unroll 4
        for (int kp = 0; kp < 128; kp++) {
            int k = kbase + 2 * kp;
            ulonglong2 w0 = *(const ulonglong2*)&Wr[(size_t)(2 * kp) * HIDDEN + j4];
            ulonglong2 w1 = *(const ulonglong2*)&Wr[(size_t)(2 * kp + 1) * HIDDEN + j4];
            u64 hk0 = h0d[k], hk0b = h0d[k + 1];
            u64 hk1 = h1d[k], hk1b = h1d[k + 1];
            acc00 = fma2(hk0,  w0.x, acc00); acc01 = fma2(hk0,  w0.y, acc01);
            acc10 = fma2(hk1,  w0.x, acc10); acc11 = fma2(hk1,  w0.y, acc11);
            acc00 = fma2(hk0b, w1.x, acc00); acc01 = fma2(hk0b, w1.y, acc01);
            acc10 = fma2(hk1b, w1.x, acc10); acc11 = fma2(hk1b, w1.y, acc11);
        }

        if (half == 1) {
            part[lt][0] = acc00; part[lt][1] = acc01;
            part[lt][2] = acc10; part[lt][3] = acc11;
        }
        __syncthreads();

        if (half == 0) {
            acc00 = add2(acc00, part[lt][0]); acc01 = add2(acc01, part[lt][1]);
            acc10 = add2(acc10, part[lt][2]); acc11 = add2(acc11, part[lt][3]);

            float2 u00 = unp2(acc00), u01 = unp2(acc01);
            float2 u10 = unp2(acc10), u11 = unp2(acc11);
            float4 r0 = make_float4(tanhf(u00.x), tanhf(u00.y), tanhf(u01.x), tanhf(u01.y));
            float4 r1 = make_float4(tanhf(u10.x), tanhf(u10.y), tanhf(u11.x), tanhf(u11.y));

            h0d[j4+0]=dup2(r0.x); h0d[j4+1]=dup2(r0.y); h0d[j4+2]=dup2(r0.z); h0d[j4+3]=dup2(r0.w);
            h1d[j4+0]=dup2(r1.x); h1d[j4+1]=dup2(r1.y); h1d[j4+2]=dup2(r1.z); h1d[j4+3]=dup2(r1.w);

            size_t row0 = ((size_t)b0 * SEQ + t) * KDIM + dir * HIDDEN + j4;
            size_t row1 = ((size_t)b1 * SEQ + t) * KDIM + dir * HIDDEN + j4;
            __half2 p00 = __floats2half2_rn(r0.x, r0.y);
            __half2 p01 = __floats2half2_rn(r0.z, r0.w);
            __half2 p10 = __floats2half2_rn(r1.x, r1.y);
            __half2 p11 = __floats2half2_rn(r1.z, r1.w);
            *(uint2*)&gA[row0] = make_uint2(*(uint32_t*)&p00, *(uint32_t*)&p01);
            *(uint2*)&gA[row1] = make_uint2(*(uint32_t*)&p10, *(uint32_t*)&p11);
        }
        __syncthreads();
    }
}

// ============ Kernel 4: FC GEMM via mma.sync fp16, single pass ============
// CTA 128x128, BK=32, 4-stage cp.async pipeline. smem rows padded to 80B.
#define RSB    80
#define TILEB  (128 * RSB)      // 10240
#define STAGEB (2 * TILEB)      // 20480: [A tile][B tile]
#define FC_SMEM (4 * STAGEB)    // 81920

__device__ __forceinline__ void fc_load_stage(
    uint32_t base, int kc, int m0, int n0, int tid)
{
    const int k0 = kc * 32;
    const __half* srcA = gA + (size_t)m0 * KDIM;
    const __half* srcB = gB + (size_t)n0 * KDIM;
    #pragma unroll
    for (int j = 0; j < 2; j++) {
        int u = tid + 256 * j;
        int row = u >> 2, c = u & 3;
        cpa16(base + row * RSB + c * 16, srcA + (size_t)row * KDIM + k0 + c * 8);
    }
    #pragma unroll
    for (int j = 0; j < 2; j++) {
        int u = tid + 256 * j;
        int row = u >> 2, c = u & 3;
        cpa16(base + TILEB + row * RSB + c * 16, srcB + (size_t)row * KDIM + k0 + c * 8);
    }
    cpa_commit();
}

__global__ __launch_bounds__(256, 2) void fc_kernel(
    const float* __restrict__ bfc, float* __restrict__ out)
{
    extern __shared__ char smem[];
    const uint32_t sb = smem_u32(smem);
    const int tid = threadIdx.x, lane = tid & 31, wid = tid >> 5;
    const int mw = wid & 1, nw = wid >> 1;
    const int m0 = blockIdx.x * 128, n0 = blockIdx.y * 128;

    const int q = lane >> 3, r = lane & 7;
    const uint32_t aOff = (uint32_t)((mw * 64 + (q & 1) * 8 + r) * RSB + ((q >> 1) * 8) * 2);
    const uint32_t bOff = (uint32_t)((nw * 32 + (q >> 1) * 8 + r) * RSB + ((q & 1) * 8) * 2);

    float acc[4][4][4];
    #pragma unroll
    for (int i = 0; i < 4; i++)
        #pragma unroll
        for (int j = 0; j < 4; j++) {
            acc[i][j][0] = 0.f; acc[i][j][1] = 0.f;
            acc[i][j][2] = 0.f; acc[i][j][3] = 0.f;
        }

    fc_load_stage(sb + 0 * STAGEB, 0, m0, n0, tid);
    fc_load_stage(sb + 1 * STAGEB, 1, m0, n0, tid);
    fc_load_stage(sb + 2 * STAGEB, 2, m0, n0, tid);

    for (int kc = 0; kc < 32; kc++) {
        if (kc < 30) cpa_wait2();
        else if (kc == 30) cpa_wait1();
        else cpa_wait0();
        __syncthreads();

        const uint32_t bb = sb + (uint32_t)(kc & 3) * STAGEB;

        #pragma unroll
        for (int j16 = 0; j16 < 2; j16++) {
            const uint32_t kb = (uint32_t)j16 * 32;
            uint32_t ah[4][4], bh[2][4];
            #pragma unroll
            for (int mf = 0; mf < 4; mf++)
                ldsm4(ah[mf], bb + aOff + mf * (16 * RSB) + kb);
            #pragma unroll
            for (int nf2 = 0; nf2 < 2; nf2++)
                ldsm4(bh[nf2], bb + TILEB + bOff + nf2 * (16 * RSB) + kb);

            #pragma unroll
            for (int mf = 0; mf < 4; mf++)
                #pragma unroll
                for (int nf2 = 0; nf2 < 2; nf2++) {
                    mma_fp16(acc[mf][nf2 * 2],     ah[mf], bh[nf2][0], bh[nf2][1]);
                    mma_fp16(acc[mf][nf2 * 2 + 1], ah[mf], bh[nf2][2], bh[nf2][3]);
                }
        }

        if (kc < 29) fc_load_stage(sb + (uint32_t)((kc + 3) & 3) * STAGEB,
                                   kc + 3, m0, n0, tid);
    }

    // epilogue: registers -> gmem with bias
    #pragma unroll
    for (int mf = 0; mf < 4; mf++) {
        const int row = m0 + mw * 64 + mf * 16 + (lane >> 2);
        #pragma unroll
        for (int nf = 0; nf < 4; nf++) {
            const int col = n0 + nw * 32 + nf * 8 + 2 * (lane & 3);
            const float2 bb2 = __ldg((const float2*)&bfc[col]);
            float2 v0 = make_float2(acc[mf][nf][0] + bb2.x, acc[mf][nf][1] + bb2.y);
            float2 v1 = make_float2(acc[mf][nf][2] + bb2.x, acc[mf][nf][3] + bb2.y);
            *(float2*)&out[(size_t)row * VOCAB + col]       = v0;
            *(float2*)&out[(size_t)(row + 8) * VOCAB + col] = v1;
        }
    }
}

// ============ launch ============
extern "C" void kernel_launch(void* const* d_in, const int* in_sizes, int n_in,
                              void* d_out, int out_size) {
    const int*   inputs = (const int*)  d_in[0];
    const float* h_prev = (const float*)d_in[1];
    const float* emb    = (const float*)d_in[2];
    const float* W_xh_f = (const float*)d_in[3];
    const float* W_hh_f = (const float*)d_in[4];
    const float* b_h_f  = (const float*)d_in[5];
    const float* W_xh_b = (const float*)d_in[6];
    const float* W_hh_b = (const float*)d_in[7];
    const float* b_h_b  = (const float*)d_in[8];
    const float* W_fc   = (const float*)d_in[9];
    const float* b_fc   = (const float*)d_in[10];
    float* out = (float*)d_out;

    cudaFuncSetAttribute(fc_kernel, cudaFuncAttributeMaxDynamicSharedMemorySize, FC_SMEM);

    pre_kernel<<<dim3(BT / 64, 16), 256>>>(inputs, emb, W_xh_f, b_h_f, W_xh_b, b_h_b);
    convw_kernel<<<dim3(KDIM / 32, VOCAB / 32), 256>>>(W_fc);
    scan_kernel<<<16, 256>>>(h_prev, W_hh_f, W_hh_b);
    fc_kernel<<<dim3(BT / 128, VOCAB / 128), 256, FC_SMEM>>>(b_fc, out);
}

// round 8
// speedup vs baseline: 9.6850x; 3.2907x over previous
#include <cuda_runtime.h>
#include <cuda_bf16.h>
#include <cuda_fp16.h>
#include <cstdint>

#define VOCAB  32000
#define EMBED  256
#define HIDDEN 512
#define BATCH  16
#define SEQ    512
#define BT     (BATCH * SEQ)   // 8192
#define KDIM   1024            // 2*HIDDEN

typedef unsigned long long u64;

// ---------------- scratch (static device arrays) ----------------
__device__ float  g_pre[2u * BT * HIDDEN];        // [dir][bt][h]
__device__ __half gA[(size_t)BT * KDIM];          // hcat fp16 [bt][k]
__device__ __half gB[(size_t)VOCAB * KDIM];       // W_fc^T fp16 [n][k]

// ---------------- f32x2 helpers ----------------
__device__ __forceinline__ u64 fma2(u64 a, u64 b, u64 c) {
    u64 d; asm("fma.rn.f32x2 %0, %1, %2, %3;" : "=l"(d) : "l"(a), "l"(b), "l"(c)); return d;
}
__device__ __forceinline__ u64 add2(u64 a, u64 b) {
    u64 d; asm("add.rn.f32x2 %0, %1, %2;" : "=l"(d) : "l"(a), "l"(b)); return d;
}
__device__ __forceinline__ u64 dup2(float x) {
    u64 d; asm("mov.b64 %0, {%1, %1};" : "=l"(d) : "f"(x)); return d;
}
__device__ __forceinline__ float2 unp2(u64 v) {
    float2 r; asm("mov.b64 {%0, %1}, %2;" : "=f"(r.x), "=f"(r.y) : "l"(v)); return r;
}

// ---------------- smem / cp.async helpers ----------------
__device__ __forceinline__ uint32_t smem_u32(const void* p) {
    uint32_t a;
    asm("{ .reg .u64 t; cvta.to.shared.u64 t, %1; cvt.u32.u64 %0, t; }" : "=r"(a) : "l"(p));
    return a;
}
__device__ __forceinline__ void cpa16(uint32_t dst, const void* src) {
    asm volatile("cp.async.cg.shared.global [%0], [%1], 16;" :: "r"(dst), "l"(src));
}
__device__ __forceinline__ void cpa_commit() { asm volatile("cp.async.commit_group;" ::: "memory"); }
__device__ __forceinline__ void cpa_wait2()  { asm volatile("cp.async.wait_group 2;"  ::: "memory"); }
__device__ __forceinline__ void cpa_wait1()  { asm volatile("cp.async.wait_group 1;"  ::: "memory"); }
__device__ __forceinline__ void cpa_wait0()  { asm volatile("cp.async.wait_group 0;"  ::: "memory"); }

// ---------------- cluster / DSMEM helpers ----------------
__device__ __forceinline__ uint32_t ctarank() {
    uint32_t r; asm("mov.u32 %0, %%cluster_ctarank;" : "=r"(r)); return r;
}
__device__ __forceinline__ void st_cluster_u64(uint32_t localAddr, uint32_t rankTo, u64 v) {
    asm volatile("{\n\t.reg .b32 ra;\n\t"
                 "mapa.shared::cluster.u32 ra, %0, %1;\n\t"
                 "st.shared::cluster.b64 [ra], %2;\n\t}"
                 :: "r"(localAddr), "r"(rankTo), "l"(v) : "memory");
}
__device__ __forceinline__ void cluster_sync() {
    asm volatile("barrier.cluster.arrive.aligned;" ::: "memory");
    asm volatile("barrier.cluster.wait.aligned;"   ::: "memory");
}

// ---------------- mma.sync / ldmatrix ----------------
__device__ __forceinline__ void ldsm4(uint32_t* r, uint32_t addr) {
    asm volatile("ldmatrix.sync.aligned.m8n8.x4.shared.b16 {%0,%1,%2,%3}, [%4];"
                 : "=r"(r[0]), "=r"(r[1]), "=r"(r[2]), "=r"(r[3]) : "r"(addr));
}
__device__ __forceinline__ void mma_fp16(float* c, const uint32_t* a, uint32_t b0, uint32_t b1) {
    asm volatile("mma.sync.aligned.m16n8k16.row.col.f32.f16.f16.f32 "
                 "{%0,%1,%2,%3}, {%4,%5,%6,%7}, {%8,%9}, {%0,%1,%2,%3};"
                 : "+f"(c[0]), "+f"(c[1]), "+f"(c[2]), "+f"(c[3])
                 : "r"(a[0]), "r"(a[1]), "r"(a[2]), "r"(a[3]), "r"(b0), "r"(b1));
}

// ============ Kernel 1: pre = gather(emb) @ W_xh + b ============
__global__ __launch_bounds__(256) void pre_kernel(
    const int* __restrict__ inputs, const float* __restrict__ emb,
    const float* __restrict__ Wxf, const float* __restrict__ bhf,
    const float* __restrict__ Wxb, const float* __restrict__ bhb)
{
    __shared__ int   toks[64];
    __shared__ float As[32][65];
    __shared__ float Bs[32][64];

    const int tid = threadIdx.x;
    const int dir = blockIdx.y >> 3;
    const int n0  = (blockIdx.y & 7) * 64;
    const int m0  = blockIdx.x * 64;
    const float* W  = dir ? Wxb : Wxf;
    const float* bh = dir ? bhb : bhf;

    if (tid < 64) toks[tid] = inputs[m0 + tid];
    __syncthreads();

    const int ty = tid >> 4, tx = tid & 15;
    const int am = tid >> 2, akq = (tid & 3) * 4;
    const int bkr = tid >> 4, bc4 = (tid & 15) * 4;
    const size_t arow = (size_t)toks[am] * EMBED;

    float acc[4][4] = {};

    for (int k0 = 0; k0 < EMBED; k0 += 32) {
        float4 a0 = *(const float4*)&emb[arow + k0 + akq];
        float4 a1 = *(const float4*)&emb[arow + k0 + 16 + akq];
        float4 b0 = *(const float4*)&W[(size_t)(k0 + bkr) * HIDDEN + n0 + bc4];
        float4 b1 = *(const float4*)&W[(size_t)(k0 + bkr + 16) * HIDDEN + n0 + bc4];
        __syncthreads();
        As[akq + 0][am] = a0.x; As[akq + 1][am] = a0.y;
        As[akq + 2][am] = a0.z; As[akq + 3][am] = a0.w;
        As[akq + 16][am] = a1.x; As[akq + 17][am] = a1.y;
        As[akq + 18][am] = a1.z; As[akq + 19][am] = a1.w;
        *(float4*)&Bs[bkr][bc4]      = b0;
        *(float4*)&Bs[bkr + 16][bc4] = b1;
        __syncthreads();
        #pragma unroll
        for (int k = 0; k < 32; k++) {
            float4 bv = *(const float4*)&Bs[k][tx * 4];
            #pragma unroll
            for (int i = 0; i < 4; i++) {
                float a = As[k][ty * 4 + i];
                acc[i][0] += a * bv.x; acc[i][1] += a * bv.y;
                acc[i][2] += a * bv.z; acc[i][3] += a * bv.w;
            }
        }
    }

    float4 bias = *(const float4*)&bh[n0 + tx * 4];
    #pragma unroll
    for (int i = 0; i < 4; i++) {
        int row = m0 + ty * 4 + i;
        float4 o = make_float4(acc[i][0] + bias.x, acc[i][1] + bias.y,
                               acc[i][2] + bias.z, acc[i][3] + bias.w);
        *(float4*)&g_pre[((size_t)dir * BT + row) * HIDDEN + n0 + tx * 4] = o;
    }
}

// ============ Kernel 2: W_fc transpose -> fp16 [n][k] ============
__global__ __launch_bounds__(256) void convw_kernel(const float* __restrict__ W)
{
    __shared__ float s[32][33];
    const int k0 = blockIdx.x * 32;
    const int n0 = blockIdx.y * 32;
    const int tx = threadIdx.x & 31, ty = threadIdx.x >> 5;

    #pragma unroll
    for (int j = 0; j < 4; j++) {
        int ky = ty + 8 * j;
        s[ky][tx] = W[(size_t)(k0 + ky) * VOCAB + n0 + tx];
    }
    __syncthreads();
    #pragma unroll
    for (int j = 0; j < 4; j++) {
        int ny = ty + 8 * j;
        gB[(size_t)(n0 + ny) * KDIM + k0 + tx] = __float2half_rn(s[tx][ny]);
    }
}

// ============ Kernel 3: register-resident W_hh scan ============
// 128 CTAs, cluster of 8. Cluster = (dir, batch-pair). CTA rank = 64-wide
// n-slice. W slice (512k x 64n) lives in registers: thread(warp=kq, lane=np)
// holds W2[kk] = (W[k][2np], W[k][2np+1]) for k in [kq*32, kq*32+32).
// h kept duplicated-f32x2 in smem, double-buffered; slices exchanged via DSMEM.
#define NSL 64

__global__ __launch_bounds__(512, 1) __cluster_dims__(8, 1, 1)
void scan_kernel(const float* __restrict__ hprev,
                 const float* __restrict__ Whf, const float* __restrict__ Whb)
{
    __shared__ u64 hbuf[2][HIDDEN][2];   // [buf][k][batch] dup'd pairs, 16KB
    __shared__ u64 part[16][65];         // k-reduction staging (padded)

    const int tid  = threadIdx.x;
    const int lane = tid & 31;           // np: n-pair within slice
    const int wkq  = tid >> 5;           // 0..15: k-range quarter (32 k each)
    const uint32_t rank = ctarank();     // 0..7: n-slice
    const int cid  = blockIdx.x >> 3;    // 0..15
    const int dir  = cid >> 3;
    const int bg   = cid & 7;
    const int b0   = bg * 2, b1 = b0 + 1;
    const int n0   = (int)rank * NSL;
    const float* W = dir ? Whb : Whf;
    const float* preB = g_pre + (size_t)dir * BT * HIDDEN;

    // --- load W slice into registers (one-time) ---
    u64 W2[32];
    {
        const int myn = n0 + 2 * lane;
        #pragma unroll
        for (int kk = 0; kk < 32; kk++)
            W2[kk] = *(const u64*)&W[(size_t)(wkq * 32 + kk) * HIDDEN + myn];
    }

    // --- init h buffer 0 from h_prev (full 512 k, both batches, local) ---
    for (int i = tid; i < HIDDEN; i += 512) {
        hbuf[0][i][0] = dup2(hprev[b0 * HIDDEN + i]);
        hbuf[0][i][1] = dup2(hprev[b1 * HIDDEN + i]);
    }
    __syncthreads();
    cluster_sync();   // cluster fully resident + buffers ready before DSMEM traffic

    // reduction-thread identity (tid < 64): j = tid, np = j>>1, b = j&1
    const int rnp = tid >> 1;
    const int rb  = tid & 1;
    const int rn  = n0 + rnp * 2;            // global n of my 2 outputs
    const int rbb = rb ? b1 : b0;
    const uint32_t hx_addr = smem_u32(&hbuf[0][rn][rb]);      // buf 0 base addrs
    const uint32_t hy_addr = smem_u32(&hbuf[0][rn + 1][rb]);
    const uint32_t bufstride = (uint32_t)(HIDDEN * 2 * sizeof(u64));

    for (int s = 0; s < SEQ; s++) {
        const int t   = dir ? (SEQ - 1 - s) : s;
        const int cur = s & 1, nxt = cur ^ 1;

        // prefetch pre-activation for my outputs (consumed after reduction)
        float2 prev2 = make_float2(0.f, 0.f);
        if (tid < 64)
            prev2 = *(const float2*)&preB[((size_t)rbb * SEQ + t) * HIDDEN + rn];

        // --- compute: partial dot over my 32-k range ---
        u64 a0 = 0ull, a1 = 0ull;
        #pragma unroll
        for (int kk = 0; kk < 32; kk++) {
            ulonglong2 hv = *(const ulonglong2*)&hbuf[cur][wkq * 32 + kk][0];
            a0 = fma2(hv.x, W2[kk], a0);
            a1 = fma2(hv.y, W2[kk], a1);
        }
        part[wkq][lane * 2]     = a0;
        part[wkq][lane * 2 + 1] = a1;
        __syncthreads();

        // --- reduce over 16 k-ranges, tanh, emit, broadcast ---
        if (tid < 64) {
            u64 acc = part[0][tid];
            #pragma unroll
            for (int q = 1; q < 16; q++) acc = add2(acc, part[q][tid]);
            float2 u = unp2(acc);
            float hx = tanhf(u.x + prev2.x);
            float hy = tanhf(u.y + prev2.y);

            __half2 hp = __floats2half2_rn(hx, hy);
            *(uint32_t*)&gA[((size_t)rbb * SEQ + t) * KDIM + dir * HIDDEN + rn]
                = *(uint32_t*)&hp;

            u64 dx = dup2(hx), dy = dup2(hy);
            uint32_t ax = hx_addr + (uint32_t)nxt * bufstride;
            uint32_t ay = hy_addr + (uint32_t)nxt * bufstride;
            #pragma unroll
            for (int rr = 0; rr < 8; rr++) {
                st_cluster_u64(ax, (uint32_t)rr, dx);
                st_cluster_u64(ay, (uint32_t)rr, dy);
            }
        }
        cluster_sync();   // h(s+1) visible everywhere; also orders part reuse
    }
}

// ============ Kernel 4: FC GEMM via mma.sync fp16, single pass ============
#define RSB    80
#define TILEB  (128 * RSB)
#define STAGEB (2 * TILEB)
#define FC_SMEM (4 * STAGEB)

__device__ __forceinline__ void fc_load_stage(
    uint32_t base, int kc, int m0, int n0, int tid)
{
    const int k0 = kc * 32;
    const __half* srcA = gA + (size_t)m0 * KDIM;
    const __half* srcB = gB + (size_t)n0 * KDIM;
    #pragma unroll
    for (int j = 0; j < 2; j++) {
        int u = tid + 256 * j;
        int row = u >> 2, c = u & 3;
        cpa16(base + row * RSB + c * 16, srcA + (size_t)row * KDIM + k0 + c * 8);
    }
    #pragma unroll
    for (int j = 0; j < 2; j++) {
        int u = tid + 256 * j;
        int row = u >> 2, c = u & 3;
        cpa16(base + TILEB + row * RSB + c * 16, srcB + (size_t)row * KDIM + k0 + c * 8);
    }
    cpa_commit();
}

__global__ __launch_bounds__(256, 2) void fc_kernel(
    const float* __restrict__ bfc, float* __restrict__ out)
{
    extern __shared__ char smem[];
    const uint32_t sb = smem_u32(smem);
    const int tid = threadIdx.x, lane = tid & 31, wid = tid >> 5;
    const int mw = wid & 1, nw = wid >> 1;
    const int m0 = blockIdx.x * 128, n0 = blockIdx.y * 128;

    const int q = lane >> 3, r = lane & 7;
    const uint32_t aOff = (uint32_t)((mw * 64 + (q & 1) * 8 + r) * RSB + ((q >> 1) * 8) * 2);
    const uint32_t bOff = (uint32_t)((nw * 32 + (q >> 1) * 8 + r) * RSB + ((q & 1) * 8) * 2);

    float acc[4][4][4];
    #pragma unroll
    for (int i = 0; i < 4; i++)
        #pragma unroll
        for (int j = 0; j < 4; j++) {
            acc[i][j][0] = 0.f; acc[i][j][1] = 0.f;
            acc[i][j][2] = 0.f; acc[i][j][3] = 0.f;
        }

    fc_load_stage(sb + 0 * STAGEB, 0, m0, n0, tid);
    fc_load_stage(sb + 1 * STAGEB, 1, m0, n0, tid);
    fc_load_stage(sb + 2 * STAGEB, 2, m0, n0, tid);

    for (int kc = 0; kc < 32; kc++) {
        if (kc < 30) cpa_wait2();
        else if (kc == 30) cpa_wait1();
        else cpa_wait0();
        __syncthreads();

        const uint32_t bb = sb + (uint32_t)(kc & 3) * STAGEB;

        #pragma unroll
        for (int j16 = 0; j16 < 2; j16++) {
            const uint32_t kb = (uint32_t)j16 * 32;
            uint32_t ah[4][4], bh[2][4];
            #pragma unroll
            for (int mf = 0; mf < 4; mf++)
                ldsm4(ah[mf], bb + aOff + mf * (16 * RSB) + kb);
            #pragma unroll
            for (int nf2 = 0; nf2 < 2; nf2++)
                ldsm4(bh[nf2], bb + TILEB + bOff + nf2 * (16 * RSB) + kb);

            #pragma unroll
            for (int mf = 0; mf < 4; mf++)
                #pragma unroll
                for (int nf2 = 0; nf2 < 2; nf2++) {
                    mma_fp16(acc[mf][nf2 * 2],     ah[mf], bh[nf2][0], bh[nf2][1]);
                    mma_fp16(acc[mf][nf2 * 2 + 1], ah[mf], bh[nf2][2], bh[nf2][3]);
                }
        }

        if (kc < 29) fc_load_stage(sb + (uint32_t)((kc + 3) & 3) * STAGEB,
                                   kc + 3, m0, n0, tid);
    }

    #pragma unroll
    for (int mf = 0; mf < 4; mf++) {
        const int row = m0 + mw * 64 + mf * 16 + (lane >> 2);
        #pragma unroll
        for (int nf = 0; nf < 4; nf++) {
            const int col = n0 + nw * 32 + nf * 8 + 2 * (lane & 3);
            const float2 bb2 = __ldg((const float2*)&bfc[col]);
            float2 v0 = make_float2(acc[mf][nf][0] + bb2.x, acc[mf][nf][1] + bb2.y);
            float2 v1 = make_float2(acc[mf][nf][2] + bb2.x, acc[mf][nf][3] + bb2.y);
            *(float2*)&out[(size_t)row * VOCAB + col]       = v0;
            *(float2*)&out[(size_t)(row + 8) * VOCAB + col] = v1;
        }
    }
}

// ============ launch ============
extern "C" void kernel_launch(void* const* d_in, const int* in_sizes, int n_in,
                              void* d_out, int out_size) {
    const int*   inputs = (const int*)  d_in[0];
    const float* h_prev = (const float*)d_in[1];
    const float* emb    = (const float*)d_in[2];
    const float* W_xh_f = (const float*)d_in[3];
    const float* W_hh_f = (const float*)d_in[4];
    const float* b_h_f  = (const float*)d_in[5];
    const float* W_xh_b = (const float*)d_in[6];
    const float* W_hh_b = (const float*)d_in[7];
    const float* b_h_b  = (const float*)d_in[8];
    const float* W_fc   = (const float*)d_in[9];
    const float* b_fc   = (const float*)d_in[10];
    float* out = (float*)d_out;

    cudaFuncSetAttribute(fc_kernel, cudaFuncAttributeMaxDynamicSharedMemorySize, FC_SMEM);

    pre_kernel<<<dim3(BT / 64, 16), 256>>>(inputs, emb, W_xh_f, b_h_f, W_xh_b, b_h_b);
    convw_kernel<<<dim3(KDIM / 32, VOCAB / 32), 256>>>(W_fc);
    scan_kernel<<<128, 512>>>(h_prev, W_hh_f, W_hh_b);
    fc_kernel<<<dim3(BT / 128, VOCAB / 128), 256, FC_SMEM>>>(b_fc, out);
}